// round 10
// baseline (speedup 1.0000x reference)
#include <cuda_runtime.h>
#include <cuda_bf16.h>
#include <cstdint>

#define NN 50000
#define EE 800000
#define REGSZ (NN * 128)
#define CHUNK 512
#define NCHUNK ((NN + CHUNK - 1) / CHUNK)   // 98

// ---------------- scratch (static device globals; no runtime alloc) ----------
__device__ int   g_deg[4 * NN];
__device__ int   g_cursor[4 * NN];
__device__ int   g_rowptr[4 * (NN + 1)];
__device__ float g_dinv[4 * NN];
__device__ int   g_csr_src[4 * EE];
__device__ float g_csr_coef[4 * EE];
__device__ int   g_is64[4];
__device__ int   g_chunksum[4 * NCHUNK];
__device__ int   g_chunkoff[4 * NCHUNK];
// per-pipeline intermediates (4 concurrent pipelines)
__device__ float g_xw1[4][NN * 256];
__device__ float g_xw2[4][NN * 128];
__device__ __nv_bfloat16 g_Hhi[4][NN * 256];
__device__ __nv_bfloat16 g_Hlo[4][NN * 256];
// bf16-split inputs + weights (transposed [n][k])
__device__ __nv_bfloat16 g_Xhi[4][NN * 256];
__device__ __nv_bfloat16 g_Xlo[4][NN * 256];
#define WOFF1(p) ((p) * 65536)
#define WOFF2(p) (262144 + (p) * 32768)
#define WOFFR(i) (393216 + (i) * 32768)
__device__ __nv_bfloat16 g_Whi[458752];
__device__ __nv_bfloat16 g_Wlo[458752];

// ---------------- mma.sync / cp.async helpers --------------------------------
__device__ __forceinline__ uint32_t smem_u32(const void* p) {
    uint32_t a;
    asm("{ .reg .u64 t; cvta.to.shared.u64 t, %1; cvt.u32.u64 %0, t; }" : "=r"(a) : "l"(p));
    return a;
}
__device__ __forceinline__ void ldsm4(uint32_t& r0, uint32_t& r1, uint32_t& r2, uint32_t& r3,
                                      uint32_t a) {
    asm volatile("ldmatrix.sync.aligned.m8n8.x4.shared.b16 {%0,%1,%2,%3}, [%4];"
                 : "=r"(r0), "=r"(r1), "=r"(r2), "=r"(r3) : "r"(a));
}
__device__ __forceinline__ void mma16816(float* d, const uint32_t* a, const uint32_t* b) {
    asm volatile(
        "mma.sync.aligned.m16n8k16.row.col.f32.bf16.bf16.f32 "
        "{%0,%1,%2,%3}, {%4,%5,%6,%7}, {%8,%9}, {%0,%1,%2,%3};"
        : "+f"(d[0]), "+f"(d[1]), "+f"(d[2]), "+f"(d[3])
        : "r"(a[0]), "r"(a[1]), "r"(a[2]), "r"(a[3]), "r"(b[0]), "r"(b[1]));
}
__device__ __forceinline__ void cp16(uint32_t dst, const void* src, bool pred) {
    int sz = pred ? 16 : 0;
    asm volatile("cp.async.ca.shared.global [%0], [%1], 16, %2;"
                 :: "r"(dst), "l"(src), "r"(sz) : "memory");
}
#define CP_COMMIT() asm volatile("cp.async.commit_group;" ::: "memory")

// ---------------- edge dtype sniffing + decode -------------------------------
__global__ void detect_kernel(const void* e0, const void* e1, const void* e2, const void* e3) {
    if (threadIdx.x < 4) {
        const void* p = threadIdx.x == 0 ? e0 : threadIdx.x == 1 ? e1 : threadIdx.x == 2 ? e2 : e3;
        const unsigned int* u = (const unsigned int*)p;
        unsigned int acc = 0;
        for (int i = 0; i < 64; i++) acc |= u[2 * i + 1];
        g_is64[threadIdx.x] = (acc == 0) ? 1 : 0;
    }
}

__device__ __forceinline__ int2 load_edge(const void* ep, int is64, int e) {
    int s, d;
    if (is64) {
        const long long* p = (const long long*)ep;
        s = (int)p[e];
        d = (int)p[EE + e];
    } else {
        const int* p = (const int*)ep;
        s = p[e];
        d = p[EE + e];
    }
    return make_int2(s, d);
}

// ---------------- CSR build ---------------------------------------------------
__global__ void zero_counts() {
    int i = blockIdx.x * blockDim.x + threadIdx.x;
    if (i < 4 * NN) { g_deg[i] = 0; g_cursor[i] = 0; }
}

__global__ void build_deg(const void* e0, const void* e1, const void* e2, const void* e3) {
    int e = blockIdx.x * blockDim.x + threadIdx.x;
    int r = blockIdx.y;
    if (e >= EE) return;
    const void* ep = r == 0 ? e0 : r == 1 ? e1 : r == 2 ? e2 : e3;
    int2 sd = load_edge(ep, g_is64[r], e);
    atomicAdd(&g_deg[r * NN + sd.y], 1);
}

__global__ void calc_dinv() {
    int i = blockIdx.x * blockDim.x + threadIdx.x;
    if (i < 4 * NN) g_dinv[i] = rsqrtf((float)g_deg[i] + 1.0f);
}

__global__ void scan_p1() {
    int r = blockIdx.y;
    int i = blockIdx.x * CHUNK + threadIdx.x;
    int v = (i < NN) ? g_deg[r * NN + i] : 0;
    __shared__ int sh[CHUNK];
    sh[threadIdx.x] = v;
    __syncthreads();
    for (int off = CHUNK / 2; off > 0; off >>= 1) {
        if (threadIdx.x < off) sh[threadIdx.x] += sh[threadIdx.x + off];
        __syncthreads();
    }
    if (threadIdx.x == 0) g_chunksum[r * NCHUNK + blockIdx.x] = sh[0];
}

__global__ void scan_p2() {
    int r = blockIdx.x;
    __shared__ int sh[128];
    int v = (threadIdx.x < NCHUNK) ? g_chunksum[r * NCHUNK + threadIdx.x] : 0;
    sh[threadIdx.x] = v;
    __syncthreads();
    for (int off = 1; off < 128; off <<= 1) {
        int t = (threadIdx.x >= off) ? sh[threadIdx.x - off] : 0;
        __syncthreads();
        sh[threadIdx.x] += t;
        __syncthreads();
    }
    if (threadIdx.x < NCHUNK) g_chunkoff[r * NCHUNK + threadIdx.x] = sh[threadIdx.x] - v;
    if (threadIdx.x == 127) g_rowptr[r * (NN + 1) + NN] = sh[127];
}

__global__ void scan_p3() {
    int r = blockIdx.y;
    int i = blockIdx.x * CHUNK + threadIdx.x;
    int v = (i < NN) ? g_deg[r * NN + i] : 0;
    __shared__ int sh[CHUNK];
    sh[threadIdx.x] = v;
    __syncthreads();
    for (int off = 1; off < CHUNK; off <<= 1) {
        int t = (threadIdx.x >= off) ? sh[threadIdx.x - off] : 0;
        __syncthreads();
        sh[threadIdx.x] += t;
        __syncthreads();
    }
    if (i < NN)
        g_rowptr[r * (NN + 1) + i] = g_chunkoff[r * NCHUNK + blockIdx.x] + sh[threadIdx.x] - v;
}

__global__ void build_csr(const void* e0, const void* e1, const void* e2, const void* e3) {
    int e = blockIdx.x * blockDim.x + threadIdx.x;
    int r = blockIdx.y;
    if (e >= EE) return;
    const void* ep = r == 0 ? e0 : r == 1 ? e1 : r == 2 ? e2 : e3;
    int2 sd = load_edge(ep, g_is64[r], e);
    int pos = g_rowptr[r * (NN + 1) + sd.y] + atomicAdd(&g_cursor[r * NN + sd.y], 1);
    g_csr_src[r * EE + pos] = sd.x;
    g_csr_coef[r * EE + pos] = g_dinv[r * NN + sd.x] * g_dinv[r * NN + sd.y];
}

// ---------------- bf16 split conversions (batched) ----------------------------
__global__ void convA4(const float* __restrict__ x0, const float* __restrict__ x1,
                       const float* __restrict__ x2, const float* __restrict__ x3,
                       __nv_bfloat16* __restrict__ hi, __nv_bfloat16* __restrict__ lo,
                       int n4) {
    int i = blockIdx.x * 256 + threadIdx.x;
    if (i >= n4) return;
    int p = blockIdx.y;
    const float* x = p == 0 ? x0 : p == 1 ? x1 : p == 2 ? x2 : x3;
    size_t off = (size_t)p * NN * 256;
    float4 v = ((const float4*)x)[i];
    __nv_bfloat16 h0 = __float2bfloat16(v.x);
    __nv_bfloat16 h1 = __float2bfloat16(v.y);
    __nv_bfloat16 h2 = __float2bfloat16(v.z);
    __nv_bfloat16 h3 = __float2bfloat16(v.w);
    __nv_bfloat162* hp = (__nv_bfloat162*)&hi[off + (size_t)i * 4];
    hp[0] = __nv_bfloat162(h0, h1);
    hp[1] = __nv_bfloat162(h2, h3);
    __nv_bfloat162* lp = (__nv_bfloat162*)&lo[off + (size_t)i * 4];
    lp[0] = __nv_bfloat162(__float2bfloat16(v.x - __bfloat162float(h0)),
                           __float2bfloat16(v.y - __bfloat162float(h1)));
    lp[1] = __nv_bfloat162(__float2bfloat16(v.z - __bfloat162float(h2)),
                           __float2bfloat16(v.w - __bfloat162float(h3)));
}

struct WArgs {
    const float* W[10];
    int N[10];
    int off[10];
};
__global__ void convW10(WArgs a, __nv_bfloat16* __restrict__ hi, __nv_bfloat16* __restrict__ lo) {
    int m = blockIdx.y;
    int i = blockIdx.x * 256 + threadIdx.x;
    int N = a.N[m];
    if (i >= N * 256) return;
    int n = i >> 8, k = i & 255;
    float v = a.W[m][k * N + n];
    __nv_bfloat16 h = __float2bfloat16(v);
    hi[a.off[m] + i] = h;
    lo[a.off[m] + i] = __float2bfloat16(v - __bfloat162float(h));
}

// ---------------- mma.sync GEMM, 3-stage cp.async K32 pipeline ---------------
#define KC 32
#define LDA 40
#define S_AHI 0
#define S_ALO (128 * LDA)
#define S_BHI (2 * 128 * LDA)
#define S_BLO (2 * 128 * LDA + 64 * LDA)
#define STG_E (2 * 128 * LDA + 2 * 64 * LDA)   // 15360 elems = 30720 B/stage
#define NSTG 3
#define SMB_GEMM (NSTG * STG_E * 2)            // 92160 B

__global__ void __launch_bounds__(256, 2) gemm_mma(
    const __nv_bfloat16* __restrict__ Ahi, const __nv_bfloat16* __restrict__ Alo,
    const __nv_bfloat16* __restrict__ Bhi, const __nv_bfloat16* __restrict__ Blo,
    float* __restrict__ C, int M, int Ntot,
    const float* __restrict__ bias, const float* __restrict__ P,
    const float* __restrict__ Q, int comb) {
    extern __shared__ __nv_bfloat16 sm[];
    uint32_t sb = smem_u32(sm);
    int tid = threadIdx.x, lane = tid & 31, w = tid >> 5;
    int wm = w & 3, wn = w >> 2;
    int m0 = blockIdx.y * 128, n0 = blockIdx.x * 64;

    float acc[2][4][4];
#pragma unroll
    for (int mi = 0; mi < 2; mi++)
#pragma unroll
        for (int ni = 0; ni < 4; ni++)
#pragma unroll
            for (int q = 0; q < 4; q++) acc[mi][ni][q] = 0.0f;

    int st_row = tid >> 2;
    int st_col = (tid & 3) * 8;

    uint32_t a_off[2], b_off[2];
#pragma unroll
    for (int mi = 0; mi < 2; mi++)
        a_off[mi] = (uint32_t)((wm * 32 + mi * 16 + (lane & 15)) * LDA + (lane >> 4) * 8);
#pragma unroll
    for (int bt = 0; bt < 2; bt++)
        b_off[bt] = (uint32_t)((wn * 32 + bt * 16 + ((lane >> 4) << 3) + (lane & 7)) * LDA +
                               ((lane >> 3) & 1) * 8);

    auto issue = [&](int c) {
        int k0 = c * KC;
        uint32_t base = sb + (uint32_t)((c % NSTG) * STG_E * 2);
#pragma unroll
        for (int i = 0; i < 2; i++) {
            int row = st_row + i * 64;
            int gr = m0 + row;
            bool ok = gr < M;
            int grc = ok ? gr : (M - 1);
            cp16(base + (uint32_t)((S_AHI + row * LDA + st_col) * 2),
                 &Ahi[(size_t)grc * 256 + k0 + st_col], ok);
            cp16(base + (uint32_t)((S_ALO + row * LDA + st_col) * 2),
                 &Alo[(size_t)grc * 256 + k0 + st_col], ok);
        }
        cp16(base + (uint32_t)((S_BHI + st_row * LDA + st_col) * 2),
             &Bhi[(size_t)(n0 + st_row) * 256 + k0 + st_col], true);
        cp16(base + (uint32_t)((S_BLO + st_row * LDA + st_col) * 2),
             &Blo[(size_t)(n0 + st_row) * 256 + k0 + st_col], true);
        CP_COMMIT();
    };

    issue(0);
    issue(1);

#pragma unroll
    for (int c = 0; c < 8; c++) {
        if (c < 7) asm volatile("cp.async.wait_group 1;" ::: "memory");
        else       asm volatile("cp.async.wait_group 0;" ::: "memory");
        __syncthreads();
        if (c + 2 < 8) issue(c + 2);

        uint32_t base = sb + (uint32_t)((c % NSTG) * STG_E * 2);
#pragma unroll
        for (int ks = 0; ks < 2; ks++) {
            int k = ks * 16;
            uint32_t aH[2][4], aL[2][4], bH[4][2], bL[4][2];
#pragma unroll
            for (int mi = 0; mi < 2; mi++) {
                ldsm4(aH[mi][0], aH[mi][1], aH[mi][2], aH[mi][3],
                      base + ((S_AHI + a_off[mi] + k) << 1));
                ldsm4(aL[mi][0], aL[mi][1], aL[mi][2], aL[mi][3],
                      base + ((S_ALO + a_off[mi] + k) << 1));
            }
#pragma unroll
            for (int bt = 0; bt < 2; bt++) {
                uint32_t r0, r1, r2, r3;
                ldsm4(r0, r1, r2, r3, base + ((S_BHI + b_off[bt] + k) << 1));
                bH[bt * 2][0] = r0; bH[bt * 2][1] = r1;
                bH[bt * 2 + 1][0] = r2; bH[bt * 2 + 1][1] = r3;
                ldsm4(r0, r1, r2, r3, base + ((S_BLO + b_off[bt] + k) << 1));
                bL[bt * 2][0] = r0; bL[bt * 2][1] = r1;
                bL[bt * 2 + 1][0] = r2; bL[bt * 2 + 1][1] = r3;
            }
#pragma unroll
            for (int mi = 0; mi < 2; mi++)
#pragma unroll
                for (int ni = 0; ni < 4; ni++) {
                    mma16816(acc[mi][ni], aH[mi], bH[ni]);
                    mma16816(acc[mi][ni], aH[mi], bL[ni]);
                    mma16816(acc[mi][ni], aL[mi], bH[ni]);
                }
        }
    }

#pragma unroll
    for (int mi = 0; mi < 2; mi++) {
#pragma unroll
        for (int ni = 0; ni < 4; ni++) {
            int col = n0 + wn * 32 + ni * 8 + (lane & 3) * 2;
            int r_lo = m0 + wm * 32 + mi * 16 + (lane >> 2);
            int r_hi = r_lo + 8;
#pragma unroll
            for (int half = 0; half < 2; half++) {
                int row = half ? r_hi : r_lo;
                if (row >= M) continue;
                float2 o;
                o.x = acc[mi][ni][half * 2 + 0];
                o.y = acc[mi][ni][half * 2 + 1];
                size_t base = (size_t)row * Ntot + col;
                if (comb) {
                    o.x += bias[col] + 0.5f * (P[base] + Q[base]);
                    o.y += bias[col + 1] + 0.5f * (P[base + 1] + Q[base + 1]);
                }
                *(float2*)&C[base] = o;
            }
        }
    }
}

// ---------------- GCN aggregation (fused self-loop+bias+lrelu) ----------------
template <int F, bool EMIT16>
__global__ void agg_kernel(const float* __restrict__ xw, const float* __restrict__ bias,
                           float* __restrict__ out, __nv_bfloat16* __restrict__ ohi,
                           __nv_bfloat16* __restrict__ olo, int r) {
    int v = blockIdx.x;
    int t = threadIdx.x;  // 128 threads
    constexpr int J = F / 128;
    float acc[J];
#pragma unroll
    for (int j = 0; j < J; j++) acc[j] = 0.0f;

    const int* rp = &g_rowptr[r * (NN + 1)];
    const int* cs = &g_csr_src[r * EE];
    const float* cc = &g_csr_coef[r * EE];

    int beg = rp[v], end = rp[v + 1];
    for (int e = beg; e < end; e++) {
        int s = cs[e];
        float c = cc[e];
#pragma unroll
        for (int j = 0; j < J; j++)
            acc[j] += c * __ldg(&xw[s * F + t + j * 128]);
    }
    float dv = g_dinv[r * NN + v];
    float dv2 = dv * dv;
#pragma unroll
    for (int j = 0; j < J; j++) {
        float val = acc[j] + xw[v * F + t + j * 128] * dv2 + bias[t + j * 128];
        val = (val >= 0.0f) ? val : 0.2f * val;
        if (EMIT16) {
            __nv_bfloat16 h = __float2bfloat16(val);
            ohi[(size_t)v * F + t + j * 128] = h;
            olo[(size_t)v * F + t + j * 128] = __float2bfloat16(val - __bfloat162float(h));
        } else {
            out[(size_t)v * F + t + j * 128] = val;
        }
    }
}

// ---------------- launch ------------------------------------------------------
extern "C" void kernel_launch(void* const* d_in, const int* in_sizes, int n_in,
                              void* d_out, int out_size) {
    const float* x[4] = {(const float*)d_in[0], (const float*)d_in[1],
                         (const float*)d_in[2], (const float*)d_in[3]};
    const void* ed[4] = {d_in[4], d_in[5], d_in[6], d_in[7]};
    const float* W1[4] = {(const float*)d_in[8], (const float*)d_in[10],
                          (const float*)d_in[16], (const float*)d_in[18]};
    const float* B1[4] = {(const float*)d_in[9], (const float*)d_in[11],
                          (const float*)d_in[17], (const float*)d_in[19]};
    const float* W2[4] = {(const float*)d_in[12], (const float*)d_in[14],
                          (const float*)d_in[20], (const float*)d_in[22]};
    const float* B2[4] = {(const float*)d_in[13], (const float*)d_in[15],
                          (const float*)d_in[21], (const float*)d_in[23]};
    float* out = (float*)d_out;

    float *xw1b, *xw2b;
    __nv_bfloat16 *xhi, *xlo, *hhib, *hlob, *whi, *wlo;
    cudaGetSymbolAddress((void**)&xw1b, g_xw1);
    cudaGetSymbolAddress((void**)&xw2b, g_xw2);
    cudaGetSymbolAddress((void**)&xhi, g_Xhi);
    cudaGetSymbolAddress((void**)&xlo, g_Xlo);
    cudaGetSymbolAddress((void**)&hhib, g_Hhi);
    cudaGetSymbolAddress((void**)&hlob, g_Hlo);
    cudaGetSymbolAddress((void**)&whi, g_Whi);
    cudaGetSymbolAddress((void**)&wlo, g_Wlo);

    cudaFuncSetAttribute(gemm_mma, cudaFuncAttributeMaxDynamicSharedMemorySize, SMB_GEMM);

    // EXACTLY 3 created streams (R8-proven safe); events are cost-free
    static cudaStream_t sCSR = nullptr, sAggA = nullptr, sAggB = nullptr;
    static cudaEvent_t evRoot = nullptr, evCSR = nullptr;
    static cudaEvent_t evG1[4], evA1[4], evG2[4], evA2[4];
    if (!sCSR) {
        cudaStreamCreateWithFlags(&sCSR, cudaStreamNonBlocking);
        cudaStreamCreateWithFlags(&sAggA, cudaStreamNonBlocking);
        cudaStreamCreateWithFlags(&sAggB, cudaStreamNonBlocking);
        cudaEventCreateWithFlags(&evRoot, cudaEventDisableTiming);
        cudaEventCreateWithFlags(&evCSR, cudaEventDisableTiming);
        for (int p = 0; p < 4; p++) {
            cudaEventCreateWithFlags(&evG1[p], cudaEventDisableTiming);
            cudaEventCreateWithFlags(&evA1[p], cudaEventDisableTiming);
            cudaEventCreateWithFlags(&evG2[p], cudaEventDisableTiming);
            cudaEventCreateWithFlags(&evA2[p], cudaEventDisableTiming);
        }
    }

    // ---- fork CSR chain onto sCSR ----
    cudaEventRecord(evRoot, 0);
    cudaStreamWaitEvent(sCSR, evRoot, 0);
    detect_kernel<<<1, 32, 0, sCSR>>>(ed[0], ed[1], ed[2], ed[3]);
    zero_counts<<<(4 * NN + 255) / 256, 256, 0, sCSR>>>();
    build_deg<<<dim3((EE + 255) / 256, 4), 256, 0, sCSR>>>(ed[0], ed[1], ed[2], ed[3]);
    calc_dinv<<<(4 * NN + 255) / 256, 256, 0, sCSR>>>();
    scan_p1<<<dim3(NCHUNK, 4), CHUNK, 0, sCSR>>>();
    scan_p2<<<4, 128, 0, sCSR>>>();
    scan_p3<<<dim3(NCHUNK, 4), CHUNK, 0, sCSR>>>();
    build_csr<<<dim3((EE + 255) / 256, 4), 256, 0, sCSR>>>(ed[0], ed[1], ed[2], ed[3]);
    cudaEventRecord(evCSR, sCSR);

    // ---- conversions on the GEMM channel (stream 0) ----
    WArgs wa;
    for (int p = 0; p < 4; p++) {
        wa.W[p] = W1[p];     wa.N[p] = 256;     wa.off[p] = WOFF1(p);
        wa.W[4 + p] = W2[p]; wa.N[4 + p] = 128; wa.off[4 + p] = WOFF2(p);
    }
    wa.W[8] = (const float*)d_in[24]; wa.N[8] = 128; wa.off[8] = WOFFR(0);
    wa.W[9] = (const float*)d_in[26]; wa.N[9] = 128; wa.off[9] = WOFFR(1);
    convW10<<<dim3(256, 10), 256>>>(wa, whi, wlo);
    const int n4 = NN * 256 / 4;
    convA4<<<dim3((n4 + 255) / 256, 4), 256>>>(x[0], x[1], x[2], x[3], xhi, xlo, n4);

    dim3 g1(4, (NN + 127) / 128);   // Ntot=256
    dim3 g2(2, (NN + 127) / 128);   // Ntot=128
    const size_t XSZ = (size_t)NN * 256;
    const size_t X2SZ = (size_t)NN * 128;

    cudaStream_t aggS[4] = {sAggA, sAggB, sAggA, sAggB};

    // ---- GEMM channel: all layer-1 GEMMs back-to-back on stream 0 ----
    for (int p = 0; p < 4; p++) {
        gemm_mma<<<g1, 256, SMB_GEMM>>>(xhi + p * XSZ, xlo + p * XSZ, whi + WOFF1(p),
                                        wlo + WOFF1(p), xw1b + p * XSZ, NN, 256,
                                        nullptr, nullptr, nullptr, 0);
        cudaEventRecord(evG1[p], 0);
        cudaStreamWaitEvent(aggS[p], evG1[p], 0);
        cudaStreamWaitEvent(aggS[p], evCSR, 0);
        agg_kernel<256, true><<<NN, 128, 0, aggS[p]>>>(xw1b + p * XSZ, B1[p], nullptr,
                                                       hhib + p * XSZ, hlob + p * XSZ, p);
        cudaEventRecord(evA1[p], aggS[p]);
    }
    // ---- layer-2 GEMMs on stream 0, each gated on its agg1 ----
    for (int p = 0; p < 4; p++) {
        cudaStreamWaitEvent(0, evA1[p], 0);
        gemm_mma<<<g2, 256, SMB_GEMM>>>(hhib + p * XSZ, hlob + p * XSZ, whi + WOFF2(p),
                                        wlo + WOFF2(p), xw2b + p * X2SZ, NN, 128,
                                        nullptr, nullptr, nullptr, 0);
        cudaEventRecord(evG2[p], 0);
        cudaStreamWaitEvent(aggS[p], evG2[p], 0);
        agg_kernel<128, false><<<NN, 128, 0, aggS[p]>>>(xw2b + p * X2SZ, B2[p],
                                                        out + (size_t)(2 + p) * REGSZ,
                                                        nullptr, nullptr, p);
        cudaEventRecord(evA2[p], aggS[p]);
    }

    // ---- comb GEMMs on stream 0 ----
    cudaStreamWaitEvent(0, evA2[0], 0);
    cudaStreamWaitEvent(0, evA2[2], 0);
    gemm_mma<<<g2, 256, SMB_GEMM>>>(xhi, xlo, whi + WOFFR(0), wlo + WOFFR(0), out, NN, 128,
                                    (const float*)d_in[25], out + (size_t)2 * REGSZ,
                                    out + (size_t)4 * REGSZ, 1);
    cudaStreamWaitEvent(0, evA2[1], 0);
    cudaStreamWaitEvent(0, evA2[3], 0);
    gemm_mma<<<g2, 256, SMB_GEMM>>>(xhi + XSZ, xlo + XSZ, whi + WOFFR(1), wlo + WOFFR(1),
                                    out + (size_t)REGSZ, NN, 128, (const float*)d_in[27],
                                    out + (size_t)3 * REGSZ, out + (size_t)5 * REGSZ, 1);
}

// round 12
// speedup vs baseline: 1.0126x; 1.0126x over previous
#include <cuda_runtime.h>
#include <cuda_bf16.h>
#include <cstdint>

#define NN 50000
#define EE 800000
#define REGSZ (NN * 128)
#define CHUNK 512
#define NCHUNK ((NN + CHUNK - 1) / CHUNK)   // 98

// ---------------- scratch (static device globals; no runtime alloc) ----------
__device__ int   g_deg[4 * NN];
__device__ int   g_cursor[4 * NN];
__device__ int   g_rowptr[4 * (NN + 1)];
__device__ float g_dinv[4 * NN];
__device__ int   g_csr_src[4 * EE];
__device__ float g_csr_coef[4 * EE];
__device__ int   g_is64[4];
__device__ int   g_chunksum[4 * NCHUNK];
__device__ int   g_chunkoff[4 * NCHUNK];
// per-pipeline intermediates (4 concurrent pipelines)
__device__ float g_xw1[4][NN * 256];
__device__ float g_xw2[4][NN * 128];
__device__ __nv_bfloat16 g_Hhi[4][NN * 256];
__device__ __nv_bfloat16 g_Hlo[4][NN * 256];
// bf16-split inputs + weights (transposed [n][k])
__device__ __nv_bfloat16 g_Xhi[4][NN * 256];
__device__ __nv_bfloat16 g_Xlo[4][NN * 256];
#define WOFF1(p) ((p) * 65536)
#define WOFF2(p) (262144 + (p) * 32768)
#define WOFFR(i) (393216 + (i) * 32768)
__device__ __nv_bfloat16 g_Whi[458752];
__device__ __nv_bfloat16 g_Wlo[458752];

// ---------------- mma.sync / cp.async helpers --------------------------------
__device__ __forceinline__ uint32_t smem_u32(const void* p) {
    uint32_t a;
    asm("{ .reg .u64 t; cvta.to.shared.u64 t, %1; cvt.u32.u64 %0, t; }" : "=r"(a) : "l"(p));
    return a;
}
__device__ __forceinline__ void ldsm4(uint32_t& r0, uint32_t& r1, uint32_t& r2, uint32_t& r3,
                                      uint32_t a) {
    asm volatile("ldmatrix.sync.aligned.m8n8.x4.shared.b16 {%0,%1,%2,%3}, [%4];"
                 : "=r"(r0), "=r"(r1), "=r"(r2), "=r"(r3) : "r"(a));
}
__device__ __forceinline__ void mma16816(float* d, const uint32_t* a, const uint32_t* b) {
    asm volatile(
        "mma.sync.aligned.m16n8k16.row.col.f32.bf16.bf16.f32 "
        "{%0,%1,%2,%3}, {%4,%5,%6,%7}, {%8,%9}, {%0,%1,%2,%3};"
        : "+f"(d[0]), "+f"(d[1]), "+f"(d[2]), "+f"(d[3])
        : "r"(a[0]), "r"(a[1]), "r"(a[2]), "r"(a[3]), "r"(b[0]), "r"(b[1]));
}
__device__ __forceinline__ void cp16(uint32_t dst, const void* src, bool pred) {
    int sz = pred ? 16 : 0;
    asm volatile("cp.async.ca.shared.global [%0], [%1], 16, %2;"
                 :: "r"(dst), "l"(src), "r"(sz) : "memory");
}
#define CP_COMMIT() asm volatile("cp.async.commit_group;" ::: "memory")

// ---------------- edge dtype sniffing + decode -------------------------------
__global__ void detect_kernel(const void* e0, const void* e1, const void* e2, const void* e3) {
    if (threadIdx.x < 4) {
        const void* p = threadIdx.x == 0 ? e0 : threadIdx.x == 1 ? e1 : threadIdx.x == 2 ? e2 : e3;
        const unsigned int* u = (const unsigned int*)p;
        unsigned int acc = 0;
        for (int i = 0; i < 64; i++) acc |= u[2 * i + 1];
        g_is64[threadIdx.x] = (acc == 0) ? 1 : 0;
    }
}

__device__ __forceinline__ int2 load_edge(const void* ep, int is64, int e) {
    int s, d;
    if (is64) {
        const long long* p = (const long long*)ep;
        s = (int)p[e];
        d = (int)p[EE + e];
    } else {
        const int* p = (const int*)ep;
        s = p[e];
        d = p[EE + e];
    }
    return make_int2(s, d);
}

// ---------------- CSR build ---------------------------------------------------
__global__ void zero_counts() {
    int i = blockIdx.x * blockDim.x + threadIdx.x;
    if (i < 4 * NN) { g_deg[i] = 0; g_cursor[i] = 0; }
}

__global__ void build_deg(const void* e0, const void* e1, const void* e2, const void* e3) {
    int e = blockIdx.x * blockDim.x + threadIdx.x;
    int r = blockIdx.y;
    if (e >= EE) return;
    const void* ep = r == 0 ? e0 : r == 1 ? e1 : r == 2 ? e2 : e3;
    int2 sd = load_edge(ep, g_is64[r], e);
    atomicAdd(&g_deg[r * NN + sd.y], 1);
}

__global__ void calc_dinv() {
    int i = blockIdx.x * blockDim.x + threadIdx.x;
    if (i < 4 * NN) g_dinv[i] = rsqrtf((float)g_deg[i] + 1.0f);
}

__global__ void scan_p1() {
    int r = blockIdx.y;
    int i = blockIdx.x * CHUNK + threadIdx.x;
    int v = (i < NN) ? g_deg[r * NN + i] : 0;
    __shared__ int sh[CHUNK];
    sh[threadIdx.x] = v;
    __syncthreads();
    for (int off = CHUNK / 2; off > 0; off >>= 1) {
        if (threadIdx.x < off) sh[threadIdx.x] += sh[threadIdx.x + off];
        __syncthreads();
    }
    if (threadIdx.x == 0) g_chunksum[r * NCHUNK + blockIdx.x] = sh[0];
}

__global__ void scan_p2() {
    int r = blockIdx.x;
    __shared__ int sh[128];
    int v = (threadIdx.x < NCHUNK) ? g_chunksum[r * NCHUNK + threadIdx.x] : 0;
    sh[threadIdx.x] = v;
    __syncthreads();
    for (int off = 1; off < 128; off <<= 1) {
        int t = (threadIdx.x >= off) ? sh[threadIdx.x - off] : 0;
        __syncthreads();
        sh[threadIdx.x] += t;
        __syncthreads();
    }
    if (threadIdx.x < NCHUNK) g_chunkoff[r * NCHUNK + threadIdx.x] = sh[threadIdx.x] - v;
    if (threadIdx.x == 127) g_rowptr[r * (NN + 1) + NN] = sh[127];
}

__global__ void scan_p3() {
    int r = blockIdx.y;
    int i = blockIdx.x * CHUNK + threadIdx.x;
    int v = (i < NN) ? g_deg[r * NN + i] : 0;
    __shared__ int sh[CHUNK];
    sh[threadIdx.x] = v;
    __syncthreads();
    for (int off = 1; off < CHUNK; off <<= 1) {
        int t = (threadIdx.x >= off) ? sh[threadIdx.x - off] : 0;
        __syncthreads();
        sh[threadIdx.x] += t;
        __syncthreads();
    }
    if (i < NN)
        g_rowptr[r * (NN + 1) + i] = g_chunkoff[r * NCHUNK + blockIdx.x] + sh[threadIdx.x] - v;
}

__global__ void build_csr(const void* e0, const void* e1, const void* e2, const void* e3) {
    int e = blockIdx.x * blockDim.x + threadIdx.x;
    int r = blockIdx.y;
    if (e >= EE) return;
    const void* ep = r == 0 ? e0 : r == 1 ? e1 : r == 2 ? e2 : e3;
    int2 sd = load_edge(ep, g_is64[r], e);
    int pos = g_rowptr[r * (NN + 1) + sd.y] + atomicAdd(&g_cursor[r * NN + sd.y], 1);
    g_csr_src[r * EE + pos] = sd.x;
    g_csr_coef[r * EE + pos] = g_dinv[r * NN + sd.x] * g_dinv[r * NN + sd.y];
}

// ---------------- bf16 split conversions (batched) ----------------------------
__global__ void convA4(const float* __restrict__ x0, const float* __restrict__ x1,
                       const float* __restrict__ x2, const float* __restrict__ x3,
                       __nv_bfloat16* __restrict__ hi, __nv_bfloat16* __restrict__ lo,
                       int n4) {
    int i = blockIdx.x * 256 + threadIdx.x;
    if (i >= n4) return;
    int p = blockIdx.y;
    const float* x = p == 0 ? x0 : p == 1 ? x1 : p == 2 ? x2 : x3;
    size_t off = (size_t)p * NN * 256;
    float4 v = ((const float4*)x)[i];
    __nv_bfloat16 h0 = __float2bfloat16(v.x);
    __nv_bfloat16 h1 = __float2bfloat16(v.y);
    __nv_bfloat16 h2 = __float2bfloat16(v.z);
    __nv_bfloat16 h3 = __float2bfloat16(v.w);
    __nv_bfloat162* hp = (__nv_bfloat162*)&hi[off + (size_t)i * 4];
    hp[0] = __nv_bfloat162(h0, h1);
    hp[1] = __nv_bfloat162(h2, h3);
    __nv_bfloat162* lp = (__nv_bfloat162*)&lo[off + (size_t)i * 4];
    lp[0] = __nv_bfloat162(__float2bfloat16(v.x - __bfloat162float(h0)),
                           __float2bfloat16(v.y - __bfloat162float(h1)));
    lp[1] = __nv_bfloat162(__float2bfloat16(v.z - __bfloat162float(h2)),
                           __float2bfloat16(v.w - __bfloat162float(h3)));
}

struct WArgs {
    const float* W[10];
    int N[10];
    int off[10];
};
__global__ void convW10(WArgs a, __nv_bfloat16* __restrict__ hi, __nv_bfloat16* __restrict__ lo) {
    int m = blockIdx.y;
    int i = blockIdx.x * 256 + threadIdx.x;
    int N = a.N[m];
    if (i >= N * 256) return;
    int n = i >> 8, k = i & 255;
    float v = a.W[m][k * N + n];
    __nv_bfloat16 h = __float2bfloat16(v);
    hi[a.off[m] + i] = h;
    lo[a.off[m] + i] = __float2bfloat16(v - __bfloat162float(h));
}

// ---------------- mma.sync GEMM, 3-stage cp.async K32 pipeline ---------------
// addbias: 1 -> C = A@Wt^T + bias (residual GEMM); 0 -> plain
#define KC 32
#define LDA 40
#define S_AHI 0
#define S_ALO (128 * LDA)
#define S_BHI (2 * 128 * LDA)
#define S_BLO (2 * 128 * LDA + 64 * LDA)
#define STG_E (2 * 128 * LDA + 2 * 64 * LDA)   // 15360 elems = 30720 B/stage
#define NSTG 3
#define SMB_GEMM (NSTG * STG_E * 2)            // 92160 B

__global__ void __launch_bounds__(256, 2) gemm_mma(
    const __nv_bfloat16* __restrict__ Ahi, const __nv_bfloat16* __restrict__ Alo,
    const __nv_bfloat16* __restrict__ Bhi, const __nv_bfloat16* __restrict__ Blo,
    float* __restrict__ C, int M, int Ntot,
    const float* __restrict__ bias, int addbias) {
    extern __shared__ __nv_bfloat16 sm[];
    uint32_t sb = smem_u32(sm);
    int tid = threadIdx.x, lane = tid & 31, w = tid >> 5;
    int wm = w & 3, wn = w >> 2;
    int m0 = blockIdx.y * 128, n0 = blockIdx.x * 64;

    float acc[2][4][4];
#pragma unroll
    for (int mi = 0; mi < 2; mi++)
#pragma unroll
        for (int ni = 0; ni < 4; ni++)
#pragma unroll
            for (int q = 0; q < 4; q++) acc[mi][ni][q] = 0.0f;

    int st_row = tid >> 2;
    int st_col = (tid & 3) * 8;

    uint32_t a_off[2], b_off[2];
#pragma unroll
    for (int mi = 0; mi < 2; mi++)
        a_off[mi] = (uint32_t)((wm * 32 + mi * 16 + (lane & 15)) * LDA + (lane >> 4) * 8);
#pragma unroll
    for (int bt = 0; bt < 2; bt++)
        b_off[bt] = (uint32_t)((wn * 32 + bt * 16 + ((lane >> 4) << 3) + (lane & 7)) * LDA +
                               ((lane >> 3) & 1) * 8);

    auto issue = [&](int c) {
        int k0 = c * KC;
        uint32_t base = sb + (uint32_t)((c % NSTG) * STG_E * 2);
#pragma unroll
        for (int i = 0; i < 2; i++) {
            int row = st_row + i * 64;
            int gr = m0 + row;
            bool ok = gr < M;
            int grc = ok ? gr : (M - 1);
            cp16(base + (uint32_t)((S_AHI + row * LDA + st_col) * 2),
                 &Ahi[(size_t)grc * 256 + k0 + st_col], ok);
            cp16(base + (uint32_t)((S_ALO + row * LDA + st_col) * 2),
                 &Alo[(size_t)grc * 256 + k0 + st_col], ok);
        }
        cp16(base + (uint32_t)((S_BHI + st_row * LDA + st_col) * 2),
             &Bhi[(size_t)(n0 + st_row) * 256 + k0 + st_col], true);
        cp16(base + (uint32_t)((S_BLO + st_row * LDA + st_col) * 2),
             &Blo[(size_t)(n0 + st_row) * 256 + k0 + st_col], true);
        CP_COMMIT();
    };

    issue(0);
    issue(1);

#pragma unroll
    for (int c = 0; c < 8; c++) {
        if (c < 7) asm volatile("cp.async.wait_group 1;" ::: "memory");
        else       asm volatile("cp.async.wait_group 0;" ::: "memory");
        __syncthreads();
        if (c + 2 < 8) issue(c + 2);

        uint32_t base = sb + (uint32_t)((c % NSTG) * STG_E * 2);
#pragma unroll
        for (int ks = 0; ks < 2; ks++) {
            int k = ks * 16;
            uint32_t aH[2][4], aL[2][4], bH[4][2], bL[4][2];
#pragma unroll
            for (int mi = 0; mi < 2; mi++) {
                ldsm4(aH[mi][0], aH[mi][1], aH[mi][2], aH[mi][3],
                      base + ((S_AHI + a_off[mi] + k) << 1));
                ldsm4(aL[mi][0], aL[mi][1], aL[mi][2], aL[mi][3],
                      base + ((S_ALO + a_off[mi] + k) << 1));
            }
#pragma unroll
            for (int bt = 0; bt < 2; bt++) {
                uint32_t r0, r1, r2, r3;
                ldsm4(r0, r1, r2, r3, base + ((S_BHI + b_off[bt] + k) << 1));
                bH[bt * 2][0] = r0; bH[bt * 2][1] = r1;
                bH[bt * 2 + 1][0] = r2; bH[bt * 2 + 1][1] = r3;
                ldsm4(r0, r1, r2, r3, base + ((S_BLO + b_off[bt] + k) << 1));
                bL[bt * 2][0] = r0; bL[bt * 2][1] = r1;
                bL[bt * 2 + 1][0] = r2; bL[bt * 2 + 1][1] = r3;
            }
#pragma unroll
            for (int mi = 0; mi < 2; mi++)
#pragma unroll
                for (int ni = 0; ni < 4; ni++) {
                    mma16816(acc[mi][ni], aH[mi], bH[ni]);
                    mma16816(acc[mi][ni], aH[mi], bL[ni]);
                    mma16816(acc[mi][ni], aL[mi], bH[ni]);
                }
        }
    }

#pragma unroll
    for (int mi = 0; mi < 2; mi++) {
#pragma unroll
        for (int ni = 0; ni < 4; ni++) {
            int col = n0 + wn * 32 + ni * 8 + (lane & 3) * 2;
            int r_lo = m0 + wm * 32 + mi * 16 + (lane >> 2);
            int r_hi = r_lo + 8;
#pragma unroll
            for (int half = 0; half < 2; half++) {
                int row = half ? r_hi : r_lo;
                if (row >= M) continue;
                float2 o;
                o.x = acc[mi][ni][half * 2 + 0];
                o.y = acc[mi][ni][half * 2 + 1];
                if (addbias) {
                    o.x += bias[col];
                    o.y += bias[col + 1];
                }
                *(float2*)&C[(size_t)row * Ntot + col] = o;
            }
        }
    }
}

// ---------------- GCN aggregation (fused self-loop+bias+lrelu) ----------------
// EMIT16: write bf16 hi/lo split (layer-1).  combdst (layer-2): comb += 0.5*val
template <int F, bool EMIT16>
__global__ void agg_kernel(const float* __restrict__ xw, const float* __restrict__ bias,
                           float* __restrict__ out, __nv_bfloat16* __restrict__ ohi,
                           __nv_bfloat16* __restrict__ olo, float* __restrict__ combdst,
                           int r) {
    int v = blockIdx.x;
    int t = threadIdx.x;  // 128 threads
    constexpr int J = F / 128;
    float acc[J];
#pragma unroll
    for (int j = 0; j < J; j++) acc[j] = 0.0f;

    const int* rp = &g_rowptr[r * (NN + 1)];
    const int* cs = &g_csr_src[r * EE];
    const float* cc = &g_csr_coef[r * EE];

    int beg = rp[v], end = rp[v + 1];
    for (int e = beg; e < end; e++) {
        int s = cs[e];
        float c = cc[e];
#pragma unroll
        for (int j = 0; j < J; j++)
            acc[j] += c * __ldg(&xw[s * F + t + j * 128]);
    }
    float dv = g_dinv[r * NN + v];
    float dv2 = dv * dv;
#pragma unroll
    for (int j = 0; j < J; j++) {
        size_t idx = (size_t)v * F + t + j * 128;
        float val = acc[j] + xw[idx] * dv2 + bias[t + j * 128];
        val = (val >= 0.0f) ? val : 0.2f * val;
        if (EMIT16) {
            __nv_bfloat16 h = __float2bfloat16(val);
            ohi[idx] = h;
            olo[idx] = __float2bfloat16(val - __bfloat162float(h));
        } else {
            out[idx] = val;
            combdst[idx] += 0.5f * val;
        }
    }
}

// ---------------- launch ------------------------------------------------------
extern "C" void kernel_launch(void* const* d_in, const int* in_sizes, int n_in,
                              void* d_out, int out_size) {
    const float* x[4] = {(const float*)d_in[0], (const float*)d_in[1],
                         (const float*)d_in[2], (const float*)d_in[3]};
    const void* ed[4] = {d_in[4], d_in[5], d_in[6], d_in[7]};
    const float* W1[4] = {(const float*)d_in[8], (const float*)d_in[10],
                          (const float*)d_in[16], (const float*)d_in[18]};
    const float* B1[4] = {(const float*)d_in[9], (const float*)d_in[11],
                          (const float*)d_in[17], (const float*)d_in[19]};
    const float* W2[4] = {(const float*)d_in[12], (const float*)d_in[14],
                          (const float*)d_in[20], (const float*)d_in[22]};
    const float* B2[4] = {(const float*)d_in[13], (const float*)d_in[15],
                          (const float*)d_in[21], (const float*)d_in[23]};
    float* out = (float*)d_out;

    float *xw1b, *xw2b;
    __nv_bfloat16 *xhi, *xlo, *hhib, *hlob, *whi, *wlo;
    cudaGetSymbolAddress((void**)&xw1b, g_xw1);
    cudaGetSymbolAddress((void**)&xw2b, g_xw2);
    cudaGetSymbolAddress((void**)&xhi, g_Xhi);
    cudaGetSymbolAddress((void**)&xlo, g_Xlo);
    cudaGetSymbolAddress((void**)&hhib, g_Hhi);
    cudaGetSymbolAddress((void**)&hlob, g_Hlo);
    cudaGetSymbolAddress((void**)&whi, g_Whi);
    cudaGetSymbolAddress((void**)&wlo, g_Wlo);

    cudaFuncSetAttribute(gemm_mma, cudaFuncAttributeMaxDynamicSharedMemorySize, SMB_GEMM);

    // EXACTLY 3 created streams, PLAIN (R8-proven leak-free; priorities leak 2MB)
    static cudaStream_t s1 = nullptr, s2 = nullptr, s3 = nullptr;
    static cudaEvent_t evRoot = nullptr, evConv = nullptr, evCSR = nullptr;
    static cudaEvent_t evA2_0 = nullptr, evA2_1 = nullptr;
    static cudaEvent_t evE1 = nullptr, evE2 = nullptr, evE3 = nullptr;
    if (!s1) {
        cudaStreamCreateWithFlags(&s1, cudaStreamNonBlocking);
        cudaStreamCreateWithFlags(&s2, cudaStreamNonBlocking);
        cudaStreamCreateWithFlags(&s3, cudaStreamNonBlocking);
        cudaEventCreateWithFlags(&evRoot, cudaEventDisableTiming);
        cudaEventCreateWithFlags(&evConv, cudaEventDisableTiming);
        cudaEventCreateWithFlags(&evCSR, cudaEventDisableTiming);
        cudaEventCreateWithFlags(&evA2_0, cudaEventDisableTiming);
        cudaEventCreateWithFlags(&evA2_1, cudaEventDisableTiming);
        cudaEventCreateWithFlags(&evE1, cudaEventDisableTiming);
        cudaEventCreateWithFlags(&evE2, cudaEventDisableTiming);
        cudaEventCreateWithFlags(&evE3, cudaEventDisableTiming);
    }

    // ---- fork: CSR chain onto s3 ----
    cudaEventRecord(evRoot, 0);
    cudaStreamWaitEvent(s3, evRoot, 0);
    detect_kernel<<<1, 32, 0, s3>>>(ed[0], ed[1], ed[2], ed[3]);
    zero_counts<<<(4 * NN + 255) / 256, 256, 0, s3>>>();
    build_deg<<<dim3((EE + 255) / 256, 4), 256, 0, s3>>>(ed[0], ed[1], ed[2], ed[3]);
    calc_dinv<<<(4 * NN + 255) / 256, 256, 0, s3>>>();
    scan_p1<<<dim3(NCHUNK, 4), CHUNK, 0, s3>>>();
    scan_p2<<<4, 128, 0, s3>>>();
    scan_p3<<<dim3(NCHUNK, 4), CHUNK, 0, s3>>>();
    build_csr<<<dim3((EE + 255) / 256, 4), 256, 0, s3>>>(ed[0], ed[1], ed[2], ed[3]);
    cudaEventRecord(evCSR, s3);

    // ---- conversions on stream 0 ----
    WArgs wa;
    for (int p = 0; p < 4; p++) {
        wa.W[p] = W1[p];     wa.N[p] = 256;     wa.off[p] = WOFF1(p);
        wa.W[4 + p] = W2[p]; wa.N[4 + p] = 128; wa.off[4 + p] = WOFF2(p);
    }
    wa.W[8] = (const float*)d_in[24]; wa.N[8] = 128; wa.off[8] = WOFFR(0);
    wa.W[9] = (const float*)d_in[26]; wa.N[9] = 128; wa.off[9] = WOFFR(1);
    convW10<<<dim3(256, 10), 256>>>(wa, whi, wlo);
    const int n4 = NN * 256 / 4;
    convA4<<<dim3((n4 + 255) / 256, 4), 256>>>(x[0], x[1], x[2], x[3], xhi, xlo, n4);
    cudaEventRecord(evConv, 0);
    cudaStreamWaitEvent(s1, evConv, 0);
    cudaStreamWaitEvent(s2, evConv, 0);
    cudaStreamWaitEvent(s3, evConv, 0);

    dim3 g1(4, (NN + 127) / 128);   // Ntot=256
    dim3 g2(2, (NN + 127) / 128);   // Ntot=128
    const size_t XSZ = (size_t)NN * 256;
    const size_t X2SZ = (size_t)NN * 128;

    // ---- residual GEMMs early, parallel on streams 0 and s1 ----
    // out[0..R) = x0@Wres_l + b_res_l  (stream 0; ordered before a2(0) same-stream)
    gemm_mma<<<g2, 256, SMB_GEMM>>>(xhi, xlo, whi + WOFFR(0), wlo + WOFFR(0), out, NN, 128,
                                    (const float*)d_in[25], 1);
    // out[R..2R) = x1@Wres_p + b_res_p (s1; ordered before a2(1) same-stream)
    gemm_mma<<<g2, 256, SMB_GEMM, s1>>>(xhi + XSZ, xlo + XSZ, whi + WOFFR(1), wlo + WOFFR(1),
                                        out + (size_t)REGSZ, NN, 128,
                                        (const float*)d_in[27], 1);

    // ---- symmetric per-pipeline chains (R8 topology) ----
    cudaStream_t ps[4] = {(cudaStream_t)0, s1, s2, s3};
    for (int p = 0; p < 4; p++) {
        cudaStream_t st = ps[p];
        gemm_mma<<<g1, 256, SMB_GEMM, st>>>(xhi + p * XSZ, xlo + p * XSZ, whi + WOFF1(p),
                                            wlo + WOFF1(p), xw1b + p * XSZ, NN, 256,
                                            nullptr, 0);
        if (p != 3) cudaStreamWaitEvent(st, evCSR, 0);  // s3 already ordered after CSR
        agg_kernel<256, true><<<NN, 128, 0, st>>>(xw1b + p * XSZ, B1[p], nullptr,
                                                  hhib + p * XSZ, hlob + p * XSZ,
                                                  nullptr, p);
        gemm_mma<<<g1.x ? g2 : g2, 256, SMB_GEMM, st>>>(hhib + p * XSZ, hlob + p * XSZ,
                                                        whi + WOFF2(p), wlo + WOFF2(p),
                                                        xw2b + p * X2SZ, NN, 128, nullptr, 0);
        // comb serialization: a2(2) after a2(0) [comb_l]; a2(3) after a2(1) [comb_p].
        if (p == 2) cudaStreamWaitEvent(st, evA2_0, 0);
        if (p == 3) cudaStreamWaitEvent(st, evA2_1, 0);
        agg_kernel<128, false><<<NN, 128, 0, st>>>(xw2b + p * X2SZ, B2[p],
                                                   out + (size_t)(2 + p) * REGSZ,
                                                   nullptr, nullptr,
                                                   out + (size_t)(p & 1) * REGSZ, p);
        if (p == 0) cudaEventRecord(evA2_0, st);
        if (p == 1) cudaEventRecord(evA2_1, st);
    }

    // ---- join all side streams back to origin ----
    cudaEventRecord(evE1, s1);
    cudaEventRecord(evE2, s2);
    cudaEventRecord(evE3, s3);
    cudaStreamWaitEvent(0, evE1, 0);
    cudaStreamWaitEvent(0, evE2, 0);
    cudaStreamWaitEvent(0, evE3, 0);
}